// round 6
// baseline (speedup 1.0000x reference)
#include <cuda_runtime.h>
#include <math.h>

// PyTorchCG: BS=64, N=1024, maxiter derived from out_size.
#define CG_N  1024
#define CG_BS 64
#define TS    128
#define NT    (CG_N / TS)         // 8
#define NPAIR (NT * (NT + 1) / 2) // 36
#define TILE_F  (TS * TS)
#define TILE_F4 (TILE_F / 4)

// Persistent CG state (no allocs -> __device__ globals).
__device__ float    g_r  [CG_BS * CG_N];
__device__ float    g_p  [2][CG_BS * CG_N];   // parity double buffer: p_it in [it&1]
__device__ float    g_Ap [CG_BS * CG_N];
__device__ float    g_d  [CG_BS * CG_N];      // diag(M_inv)
__device__ float    g_rz [CG_BS];
__device__ float    g_pap[CG_BS];
__device__ unsigned g_pready[CG_BS];          // highest iter whose p is published
// Packed upper-triangle tiles: [b][pair][128x128] contiguous (144 MB scratch).
__device__ __align__(16) float g_pack[(size_t)CG_BS * NPAIR * TILE_F];

__device__ __forceinline__ int tri_off(int bi) { return bi * NT - (bi * (bi - 1)) / 2; }

// ---------------------------------------------------------------------------
// Pack upper-triangle tiles of A contiguously + extract diag(M_inv).
// grid=(N/8,BS), block=256.
// ---------------------------------------------------------------------------
__global__ void __launch_bounds__(256) k_pack(const float* __restrict__ A,
                                              const float* __restrict__ Minv)
{
    const int b    = blockIdx.y;
    const int warp = threadIdx.x >> 5;
    const int lane = threadIdx.x & 31;
    const int row  = (blockIdx.x << 3) + warp;
    const int bi   = row >> 7;
    const int rloc = row & (TS - 1);

    const float4* Arow =
        reinterpret_cast<const float4*>(A + ((size_t)b * CG_N + row) * CG_N);

    for (int k = bi; k < NT; ++k) {
        float4 a = Arow[lane + 32 * k];
        const int li = tri_off(bi) + (k - bi);
        reinterpret_cast<float4*>(g_pack)
            [((size_t)b * NPAIR + li) * TILE_F4 + rloc * 32 + lane] = a;
    }
    if (lane == 0)
        g_d[(size_t)b * CG_N + row] =
            Minv[(size_t)b * CG_N * CG_N + (size_t)row * CG_N + row];
}

// ---------------------------------------------------------------------------
// Reset accumulators at the start of every replay.
// ---------------------------------------------------------------------------
__global__ void k_zero()
{
    const int b = blockIdx.x, tid = threadIdx.x;
    reinterpret_cast<float4*>(g_Ap + (size_t)b * CG_N)[tid] =
        make_float4(0.f, 0.f, 0.f, 0.f);
    if (tid == 0) g_pap[b] = 0.f;
}

// ---------------------------------------------------------------------------
// Deterministic block-wide sum over 256 threads.
// ---------------------------------------------------------------------------
__device__ __forceinline__ float block_sum(float v, float* sbuf)
{
    const int tid = threadIdx.x;
#pragma unroll
    for (int off = 16; off; off >>= 1)
        v += __shfl_xor_sync(0xffffffffu, v, off);
    if ((tid & 31) == 0) sbuf[tid >> 5] = v;
    __syncthreads();
    if (tid < 8) {
        float w = sbuf[tid];
#pragma unroll
        for (int off = 4; off; off >>= 1)
            w += __shfl_xor_sync(0x000000ffu, w, off);
        if (tid == 0) sbuf[0] = w;
    }
    __syncthreads();
    float r = sbuf[0];
    __syncthreads();
    return r;
}

// ---------------------------------------------------------------------------
// Update step for batch b, executed by one 256-thread CTA.
// Consumes g_Ap/g_pap of matvec it-1, produces p_it (if write_p), rnorm->out.
// Zeroes g_Ap / g_pap for the next matvec.
// ---------------------------------------------------------------------------
__device__ __forceinline__ void do_update(int b, int it, int ldout,
                                          float* __restrict__ out,
                                          float* sbuf, bool write_p)
{
    const int tid = threadIdx.x;
    const float rz_old = g_rz[b];
    const float alpha  = rz_old / g_pap[b];

    float rv[4], zk[4], po[4];
    float rz_p = 0.f, rr_p = 0.f;
    const float* pold = g_p[(it - 1) & 1];
#pragma unroll
    for (int k = 0; k < 4; ++k) {
        const size_t i = (size_t)b * CG_N + tid + 256 * k;
        const float ap = g_Ap[i];
        g_Ap[i] = 0.f;
        rv[k] = g_r[i] - alpha * ap;
        g_r[i] = rv[k];
        zk[k] = g_d[i] * rv[k];
        po[k] = pold[i];
        rz_p += rv[k] * zk[k];
        rr_p += rv[k] * rv[k];
    }
    const float rz_new = block_sum(rz_p, sbuf);
    const float rr     = block_sum(rr_p, sbuf);
    const float beta   = rz_new / rz_old;

    if (write_p) {
        float* pnew = g_p[it & 1];
#pragma unroll
        for (int k = 0; k < 4; ++k) {
            const size_t i = (size_t)b * CG_N + tid + 256 * k;
            pnew[i] = zk[k] + beta * po[k];
        }
    }
    if (tid == 0) {
        g_rz[b]  = rz_new;
        g_pap[b] = 0.f;
        out[(size_t)b * ldout + it] = sqrtf(rr);
    }
}

// ---------------------------------------------------------------------------
// Fused iteration kernel, grid=(NPAIR, BS):
//  - CTA x==0 (per batch) first runs update_{it-1} (if it>0, vext==null) and
//    publishes p_it via g_pready[b]=it (release).
//  - Other CTAs issue their first A-load batch, then spin on g_pready.
//  - All CTAs then run the symmetric tile matvec (R4 epilogue) on
//    v = vext ? vext : g_p[it&1], accumulating g_Ap and g_pap.
// ---------------------------------------------------------------------------
__global__ void __launch_bounds__(256) k_fused(int it,
                                               const float* __restrict__ vext,
                                               float* __restrict__ out, int ldout)
{
    const int b   = blockIdx.y;
    const int tid = threadIdx.x;

    int li = blockIdx.x, bi = 0;
    while (li >= NT - bi) { li -= NT - bi; ++bi; }
    const int  bj   = bi + li;
    const bool diag = (bi == bj);

    __shared__ float spi[TS];
    __shared__ float spj[TS];
    __shared__ float sd[8][16][33];
    __shared__ float scol[8][TS];
    __shared__ float sbuf[8];

    const bool producer = (vext == nullptr) && (it > 0) && (blockIdx.x == 0);

    if (producer) {
        do_update(b, it, ldout, out, sbuf, true);
        __threadfence();                              // release p / Ap / pap
        if (tid == 0)
            *(volatile unsigned*)&g_pready[b] = (unsigned)it;
        __syncthreads();
    }

    const int warp = tid >> 5;
    const int lane = tid & 31;

    const float4* T = reinterpret_cast<const float4*>(g_pack) +
                      ((size_t)b * NPAIR + blockIdx.x) * TILE_F4 +
                      (size_t)warp * 16 * 32;

    // issue first A batch before waiting: loads are independent of p
    float4 a0[8];
#pragma unroll
    for (int k = 0; k < 8; ++k) a0[k] = T[k * 32 + lane];

    if ((vext == nullptr) && (it > 0) && (blockIdx.x != 0)) {
        if (tid == 0) {
            while (*(volatile unsigned*)&g_pready[b] < (unsigned)it)
                __nanosleep(64);
        }
        __syncthreads();
        __threadfence();                              // acquire p writes
    }

    const float* vb = (vext != nullptr) ? (vext + (size_t)b * CG_N)
                                        : (g_p[it & 1] + (size_t)b * CG_N);
    if (tid < TS / 4)
        reinterpret_cast<float4*>(spi)[tid] =
            reinterpret_cast<const float4*>(vb + bi * TS)[tid];
    else if (tid < TS / 2)
        reinterpret_cast<float4*>(spj)[tid - TS / 4] =
            reinterpret_cast<const float4*>(vb + bj * TS)[tid - TS / 4];
    __syncthreads();

    const float4 pj4 = reinterpret_cast<const float4*>(spj)[lane];
    float4 cacc = make_float4(0.f, 0.f, 0.f, 0.f);

#pragma unroll
    for (int k = 0; k < 8; ++k) {
        sd[warp][k][lane] = a0[k].x * pj4.x + a0[k].y * pj4.y +
                            a0[k].z * pj4.z + a0[k].w * pj4.w;
        const float pir = spi[16 * warp + k];
        cacc.x += a0[k].x * pir;  cacc.y += a0[k].y * pir;
        cacc.z += a0[k].z * pir;  cacc.w += a0[k].w * pir;
    }
    {
        float4 a[8];
#pragma unroll
        for (int k = 0; k < 8; ++k) a[k] = T[(k + 8) * 32 + lane];
#pragma unroll
        for (int k = 0; k < 8; ++k) {
            sd[warp][k + 8][lane] = a[k].x * pj4.x + a[k].y * pj4.y +
                                    a[k].z * pj4.z + a[k].w * pj4.w;
            const float pir = spi[16 * warp + 8 + k];
            cacc.x += a[k].x * pir;  cacc.y += a[k].y * pir;
            cacc.z += a[k].z * pir;  cacc.w += a[k].w * pir;
        }
    }

    if (!diag) {
        scol[warp][4 * lane + 0] = cacc.x;
        scol[warp][4 * lane + 1] = cacc.y;
        scol[warp][4 * lane + 2] = cacc.z;
        scol[warp][4 * lane + 3] = cacc.w;
    }
    __syncthreads();

    // row dots -> y_bi
    const int ri = tid >> 1;
    const int hi = tid & 1;
    float s = 0.f;
#pragma unroll
    for (int j = 0; j < 16; ++j)
        s += sd[ri >> 4][ri & 15][16 * hi + j];
    s += __shfl_xor_sync(0xffffffffu, s, 1);

    float pap_c = 0.f;
    if (hi == 0) {
        atomicAdd(&g_Ap[(size_t)b * CG_N + (size_t)bi * TS + ri], s);
        pap_c = s * spi[ri];
    }

    // transpose part -> y_bj
    if (!diag && tid < TS) {
        float cs = 0.f;
#pragma unroll
        for (int w = 0; w < 8; ++w) cs += scol[w][tid];
        atomicAdd(&g_Ap[(size_t)b * CG_N + (size_t)bj * TS + tid], cs);
    }

    // pAp block reduce -> g_pap
#pragma unroll
    for (int off = 16; off; off >>= 1)
        pap_c += __shfl_xor_sync(0xffffffffu, pap_c, off);
    if (lane == 0) sbuf[warp] = pap_c;
    __syncthreads();
    if (tid == 0) {
        float t = 0.f;
#pragma unroll
        for (int w = 0; w < 8; ++w) t += sbuf[w];
        atomicAdd(&g_pap[b], diag ? t : 2.f * t);
    }
}

// ---------------------------------------------------------------------------
// Init: r0 = b - A@x0 (g_Ap), z0 = d*r0, p0 -> g_p[0], rz0, ||r0||.
// Resets g_Ap / g_pap / g_pready for this replay.  grid=BS, block=256.
// ---------------------------------------------------------------------------
__global__ void k_init(const float* __restrict__ bvec,
                       float* __restrict__ out, int ldout)
{
    __shared__ float sbuf[8];
    const int b   = blockIdx.x;
    const int tid = threadIdx.x;

    float rz_p = 0.f, rr_p = 0.f;
#pragma unroll
    for (int k = 0; k < CG_N / 256; ++k) {
        const size_t gi = (size_t)b * CG_N + tid + 256 * k;
        float dv = g_d[gi];
        float rv = bvec[gi] - g_Ap[gi];
        g_Ap[gi] = 0.f;
        float zv = dv * rv;
        g_r[gi] = rv;
        g_p[0][gi] = zv;
        rz_p += rv * zv;
        rr_p += rv * rv;
    }
    float rz = block_sum(rz_p, sbuf);
    float rr = block_sum(rr_p, sbuf);
    if (tid == 0) {
        g_rz[b]   = rz;
        g_pap[b]  = 0.f;
        g_pready[b] = 0u;                 // p_0 published
        out[(size_t)b * ldout] = sqrtf(rr);
    }
}

// ---------------------------------------------------------------------------
// Final update: emits out[.][maxiter] from the last matvec.  grid=BS.
// ---------------------------------------------------------------------------
__global__ void k_final(float* __restrict__ out, int it, int ldout)
{
    __shared__ float sbuf[8];
    do_update(blockIdx.x, it, ldout, out, sbuf, false);
}

// ---------------------------------------------------------------------------
// kernel_launch: graph-capturable sequence (55 launches).
// ---------------------------------------------------------------------------
extern "C" void kernel_launch(void* const* d_in, const int* in_sizes, int n_in,
                              void* d_out, int out_size)
{
    const float* A    = (const float*)d_in[0];
    const float* bvec = (const float*)d_in[1];
    const float* x0   = (const float*)d_in[2];
    const float* Minv = (const float*)d_in[3];
    float* out        = (float*)d_out;

    const int ldout   = out_size / CG_BS;   // maxiter + 1
    const int maxiter = ldout - 1;

    dim3 grid_pk(CG_N / 8, CG_BS);
    dim3 grid_mv(NPAIR, CG_BS);

    k_pack <<<grid_pk, 256>>>(A, Minv);
    k_zero <<<CG_BS,  256>>>();
    k_fused<<<grid_mv, 256>>>(0, x0, out, ldout);      // g_Ap = A @ x0
    k_init <<<CG_BS,  256>>>(bvec, out, ldout);

    for (int it = 0; it < maxiter; ++it)
        k_fused<<<grid_mv, 256>>>(it, nullptr, out, ldout);

    if (maxiter > 0)
        k_final<<<CG_BS, 256>>>(out, maxiter, ldout);
}

// round 9
// speedup vs baseline: 1.3374x; 1.3374x over previous
#include <cuda_runtime.h>
#include <math.h>

// PyTorchCG: BS=64, N=1024, maxiter derived from out_size.
#define CG_N  1024
#define CG_BS 64
#define TS    128
#define NT    8                    // CG_N / TS
#define NPAIR 36                   // NT*(NT+1)/2
#define TILE_F  (TS * TS)
#define TILE_F4 (TILE_F / 4)
#define NCTA  576                  // 64 batches * 9 CTAs; <= 148*4 resident

// Persistent CG state (no allocs -> __device__ globals).
__device__ float    g_r  [CG_BS * CG_N];
__device__ float    g_p  [CG_BS * CG_N];
__device__ float    g_Ap [CG_BS * CG_N];
__device__ float    g_d  [CG_BS * CG_N];   // diag(M_inv)
__device__ float    g_rz [CG_BS];
__device__ float    g_pap[CG_BS];
__device__ unsigned g_count;               // barrier arrivals (self-resetting)
__device__ unsigned g_sense;               // barrier phase (monotone, replay-safe)
// Packed upper-triangle tiles: [b][pair][128x128] contiguous (144 MB scratch).
__device__ __align__(16) float g_pack[(size_t)CG_BS * NPAIR * TILE_F];

// ---------------------------------------------------------------------------
// Pack upper-triangle tiles of A contiguously + extract diag(M_inv).
// grid=(N/8,BS), block=256.
// ---------------------------------------------------------------------------
__global__ void __launch_bounds__(256) k_pack(const float* __restrict__ A,
                                              const float* __restrict__ Minv)
{
    const int b    = blockIdx.y;
    const int warp = threadIdx.x >> 5;
    const int lane = threadIdx.x & 31;
    const int row  = (blockIdx.x << 3) + warp;
    const int bi   = row >> 7;
    const int rloc = row & (TS - 1);

    const float4* Arow =
        reinterpret_cast<const float4*>(A + ((size_t)b * CG_N + row) * CG_N);

    for (int k = bi; k < NT; ++k) {
        float4 a = Arow[lane + 32 * k];
        const int li = bi * NT - (bi * (bi - 1)) / 2 + (k - bi);
        reinterpret_cast<float4*>(g_pack)
            [((size_t)b * NPAIR + li) * TILE_F4 + rloc * 32 + lane] = a;
    }
    if (lane == 0)
        g_d[(size_t)b * CG_N + row] =
            Minv[(size_t)b * CG_N * CG_N + (size_t)row * CG_N + row];
}

// ---------------------------------------------------------------------------
// Grid barrier: sense-reversing, valid because all NCTA CTAs are co-resident
// (launch_bounds(256,4): regs<=64, smem 22KB -> 4 CTAs/SM, 576 <= 148*4).
// ---------------------------------------------------------------------------
__device__ __forceinline__ void grid_barrier()
{
    __syncthreads();
    if (threadIdx.x == 0) {
        __threadfence();
        const unsigned ph = *(volatile unsigned*)&g_sense;
        if (atomicAdd(&g_count, 1u) == NCTA - 1u) {
            g_count = 0u;
            __threadfence();
            *(volatile unsigned*)&g_sense = ph + 1u;
        } else {
            while (*(volatile unsigned*)&g_sense == ph) __nanosleep(32);
        }
    }
    __syncthreads();
}

struct SM {
    float spi[TS], spj[TS];
    float sd[8][16][33];
    float scol[8][TS];
    float sbuf[16];
};

// ---------------------------------------------------------------------------
// Deterministic block sum of two values over 256 threads.
// ---------------------------------------------------------------------------
__device__ __forceinline__ void block_sum2(SM& sm, float a, float b,
                                           float& ra, float& rb)
{
    const int tid = threadIdx.x;
#pragma unroll
    for (int off = 16; off; off >>= 1) {
        a += __shfl_xor_sync(0xffffffffu, a, off);
        b += __shfl_xor_sync(0xffffffffu, b, off);
    }
    if ((tid & 31) == 0) { sm.sbuf[tid >> 5] = a; sm.sbuf[8 + (tid >> 5)] = b; }
    __syncthreads();
    if (tid < 8) {
        float wa = sm.sbuf[tid], wb = sm.sbuf[8 + tid];
#pragma unroll
        for (int off = 4; off; off >>= 1) {
            wa += __shfl_xor_sync(0x000000ffu, wa, off);
            wb += __shfl_xor_sync(0x000000ffu, wb, off);
        }
        if (tid == 0) { sm.sbuf[0] = wa; sm.sbuf[8] = wb; }
    }
    __syncthreads();
    ra = sm.sbuf[0];
    rb = sm.sbuf[8];
    __syncthreads();
}

// ---------------------------------------------------------------------------
// 4 symmetric tile-pair matvec tasks for batch b, pairs pbase+9k (R4 body).
// cg=true: read v through L2 only (__ldcg) — cross-CTA data in a persistent
// kernel must not be served from stale L1.
// ---------------------------------------------------------------------------
__device__ void mv4(SM& sm, int b, int pbase, const float* __restrict__ vb, bool cg)
{
    const int tid  = threadIdx.x;
    const int warp = tid >> 5;
    const int lane = tid & 31;

#pragma unroll 1
    for (int k4 = 0; k4 < 4; ++k4) {
        const int li = pbase + 9 * k4;
        int t = li, bi = 0;
        while (t >= NT - bi) { t -= NT - bi; ++bi; }
        const int  bj   = bi + t;
        const bool diag = (bi == bj);

        __syncthreads();                       // smem reuse across tasks
        if (tid < TS / 4) {
            const float4* s = reinterpret_cast<const float4*>(vb + bi * TS);
            reinterpret_cast<float4*>(sm.spi)[tid] = cg ? __ldcg(s + tid) : __ldg(s + tid);
        } else if (tid < TS / 2) {
            const float4* s = reinterpret_cast<const float4*>(vb + bj * TS);
            reinterpret_cast<float4*>(sm.spj)[tid - TS / 4] =
                cg ? __ldcg(s + tid - TS / 4) : __ldg(s + tid - TS / 4);
        }
        __syncthreads();

        const float4* T = reinterpret_cast<const float4*>(g_pack) +
                          ((size_t)b * NPAIR + li) * TILE_F4 +
                          (size_t)warp * 16 * 32;

        const float4 pj4 = reinterpret_cast<const float4*>(sm.spj)[lane];
        float4 cacc = make_float4(0.f, 0.f, 0.f, 0.f);

        {
            float4 a[8];
#pragma unroll
            for (int k = 0; k < 8; ++k) a[k] = T[k * 32 + lane];
#pragma unroll
            for (int k = 0; k < 8; ++k) {
                sm.sd[warp][k][lane] = a[k].x * pj4.x + a[k].y * pj4.y +
                                       a[k].z * pj4.z + a[k].w * pj4.w;
                const float pir = sm.spi[16 * warp + k];
                cacc.x += a[k].x * pir;  cacc.y += a[k].y * pir;
                cacc.z += a[k].z * pir;  cacc.w += a[k].w * pir;
            }
        }
        {
            float4 a[8];
#pragma unroll
            for (int k = 0; k < 8; ++k) a[k] = T[(k + 8) * 32 + lane];
#pragma unroll
            for (int k = 0; k < 8; ++k) {
                sm.sd[warp][k + 8][lane] = a[k].x * pj4.x + a[k].y * pj4.y +
                                           a[k].z * pj4.z + a[k].w * pj4.w;
                const float pir = sm.spi[16 * warp + 8 + k];
                cacc.x += a[k].x * pir;  cacc.y += a[k].y * pir;
                cacc.z += a[k].z * pir;  cacc.w += a[k].w * pir;
            }
        }

        if (!diag) {
            sm.scol[warp][4 * lane + 0] = cacc.x;
            sm.scol[warp][4 * lane + 1] = cacc.y;
            sm.scol[warp][4 * lane + 2] = cacc.z;
            sm.scol[warp][4 * lane + 3] = cacc.w;
        }
        __syncthreads();

        // row dots -> y_bi
        const int ri = tid >> 1;
        const int hi = tid & 1;
        float s = 0.f;
#pragma unroll
        for (int j = 0; j < 16; ++j)
            s += sm.sd[ri >> 4][ri & 15][16 * hi + j];
        s += __shfl_xor_sync(0xffffffffu, s, 1);

        float pap_c = 0.f;
        if (hi == 0) {
            atomicAdd(&g_Ap[(size_t)b * CG_N + (size_t)bi * TS + ri], s);
            pap_c = s * sm.spi[ri];
        }

        // transpose part -> y_bj
        if (!diag && tid < TS) {
            float cs = 0.f;
#pragma unroll
            for (int w = 0; w < 8; ++w) cs += sm.scol[w][tid];
            atomicAdd(&g_Ap[(size_t)b * CG_N + (size_t)bj * TS + tid], cs);
        }

        // pAp block reduce -> g_pap
#pragma unroll
        for (int off = 16; off; off >>= 1)
            pap_c += __shfl_xor_sync(0xffffffffu, pap_c, off);
        if (lane == 0) sm.sbuf[warp] = pap_c;
        __syncthreads();
        if (tid == 0) {
            float tt = 0.f;
#pragma unroll
            for (int w = 0; w < 8; ++w) tt += sm.sbuf[w];
            atomicAdd(&g_pap[b], diag ? tt : 2.f * tt);
        }
    }
}

// ---------------------------------------------------------------------------
// Persistent CG kernel.  grid = NCTA, block = 256.
// CTA c: matvec worker for batch c%64 (pairs c/64 + 9k); CTAs 0..63 are also
// the updaters for their batch.
// ---------------------------------------------------------------------------
__global__ void __launch_bounds__(256, 4) k_cg(const float* __restrict__ x0,
                                               const float* __restrict__ bvec,
                                               float* __restrict__ out,
                                               int ldout, int maxiter)
{
    __shared__ SM sm;
    const int c     = blockIdx.x;
    const int tid   = threadIdx.x;
    const int b     = c & (CG_BS - 1);
    const int pbase = c >> 6;

    // phase Z: reset accumulators for this replay
    if (c < CG_BS) {
        reinterpret_cast<float4*>(g_Ap + (size_t)c * CG_N)[tid] =
            make_float4(0.f, 0.f, 0.f, 0.f);
        if (tid == 0) g_pap[c] = 0.f;
    }
    grid_barrier();

    // phase MV0: g_Ap = A @ x0
    mv4(sm, b, pbase, x0 + (size_t)b * CG_N, false);
    grid_barrier();

    // phase INIT (CTA b < 64): r0 = b - Ap, z0 = d*r0, p0 = z0, rz0, ||r0||
    if (c < CG_BS) {
        float rz_p = 0.f, rr_p = 0.f;
#pragma unroll
        for (int k = 0; k < 4; ++k) {
            const size_t i = (size_t)b * CG_N + tid + 256 * k;
            const float dv = g_d[i];
            const float rv = __ldg(&bvec[i]) - __ldcg(&g_Ap[i]);
            g_Ap[i] = 0.f;
            const float zv = dv * rv;
            g_r[i] = rv;
            g_p[i] = zv;
            rz_p += rv * zv;
            rr_p += rv * rv;
        }
        float rz, rr;
        block_sum2(sm, rz_p, rr_p, rz, rr);
        if (tid == 0) {
            g_rz[b]  = rz;
            g_pap[b] = 0.f;
            out[(size_t)b * ldout] = sqrtf(rr);
        }
    }
    grid_barrier();

    // main loop
    for (int it = 0; it < maxiter; ++it) {
        mv4(sm, b, pbase, g_p + (size_t)b * CG_N, true);
        grid_barrier();

        if (c < CG_BS) {
            const float rz_old = g_rz[b];
            const float alpha  = rz_old / __ldcg(&g_pap[b]);

            float pv[4], rv[4], dv[4];
            float rz_p = 0.f, rr_p = 0.f;
#pragma unroll
            for (int k = 0; k < 4; ++k) {
                const size_t i = (size_t)b * CG_N + tid + 256 * k;
                const float ap = __ldcg(&g_Ap[i]);
                g_Ap[i] = 0.f;
                pv[k] = g_p[i];              // own writes: L1-safe
                dv[k] = g_d[i];
                rv[k] = g_r[i] - alpha * ap;
                g_r[i] = rv[k];
                const float zv = dv[k] * rv[k];
                rz_p += rv[k] * zv;
                rr_p += rv[k] * rv[k];
            }
            float rz_new, rr;
            block_sum2(sm, rz_p, rr_p, rz_new, rr);
            const float beta = rz_new / rz_old;

#pragma unroll
            for (int k = 0; k < 4; ++k) {
                const size_t i = (size_t)b * CG_N + tid + 256 * k;
                g_p[i] = dv[k] * rv[k] + beta * pv[k];
            }
            if (tid == 0) {
                g_rz[b]  = rz_new;
                g_pap[b] = 0.f;
                out[(size_t)b * ldout + it + 1] = sqrtf(rr);
            }
        }
        grid_barrier();
    }
}

// ---------------------------------------------------------------------------
// kernel_launch: 2 graph-capturable launches.
// ---------------------------------------------------------------------------
extern "C" void kernel_launch(void* const* d_in, const int* in_sizes, int n_in,
                              void* d_out, int out_size)
{
    const float* A    = (const float*)d_in[0];
    const float* bvec = (const float*)d_in[1];
    const float* x0   = (const float*)d_in[2];
    const float* Minv = (const float*)d_in[3];
    float* out        = (float*)d_out;

    const int ldout   = out_size / CG_BS;   // maxiter + 1
    const int maxiter = ldout - 1;

    dim3 grid_pk(CG_N / 8, CG_BS);

    k_pack<<<grid_pk, 256>>>(A, Minv);
    k_cg  <<<NCTA,    256>>>(x0, bvec, out, ldout, maxiter);
}

// round 11
// speedup vs baseline: 1.3736x; 1.0271x over previous
#include <cuda_runtime.h>
#include <math.h>

// PyTorchCG: BS=64, N=1024, maxiter derived from out_size.
#define CG_N  1024
#define CG_BS 64
#define TS    128
#define NT    8                    // CG_N / TS
#define NPAIR 36                   // NT*(NT+1)/2
#define TILE_F  (TS * TS)
#define TILE_F4 (TILE_F / 4)

// Persistent state (no allocs -> __device__ globals; zero-initialized).
__device__ float g_r2 [2][CG_BS * CG_N];
__device__ float g_p2 [2][CG_BS * CG_N];
__device__ float g_Ap3[3][CG_BS * CG_N];   // consume / accumulate / zero rotation
__device__ float g_d  [CG_BS * CG_N];      // diag(M_inv)
__device__ float g_rz2[2][CG_BS];
__device__ float g_pap3[3][CG_BS];
// Packed upper-triangle tiles: [b][pair][128x128] contiguous (144 MB scratch).
__device__ __align__(16) float g_pack[(size_t)CG_BS * NPAIR * TILE_F];

// ---------------------------------------------------------------------------
// Pack upper-triangle tiles of A contiguously + extract diag(M_inv).
// grid=(N/8,BS), block=256.
// ---------------------------------------------------------------------------
__global__ void __launch_bounds__(256) k_pack(const float* __restrict__ A,
                                              const float* __restrict__ Minv)
{
    const int b    = blockIdx.y;
    const int warp = threadIdx.x >> 5;
    const int lane = threadIdx.x & 31;
    const int row  = (blockIdx.x << 3) + warp;
    const int bi   = row >> 7;
    const int rloc = row & (TS - 1);

    const float4* Arow =
        reinterpret_cast<const float4*>(A + ((size_t)b * CG_N + row) * CG_N);

    for (int k = bi; k < NT; ++k) {
        float4 a = Arow[lane + 32 * k];
        const int li = bi * NT - (bi * (bi - 1)) / 2 + (k - bi);
        reinterpret_cast<float4*>(g_pack)
            [((size_t)b * NPAIR + li) * TILE_F4 + rloc * 32 + lane] = a;
    }
    if (lane == 0)
        g_d[(size_t)b * CG_N + row] =
            Minv[(size_t)b * CG_N * CG_N + (size_t)row * CG_N + row];
}

// ---------------------------------------------------------------------------
// Deterministic block sum of two values over 256 threads.
// ---------------------------------------------------------------------------
__device__ __forceinline__ void block_sum2(float* sbuf, float a, float b,
                                           float& ra, float& rb)
{
    const int tid = threadIdx.x;
#pragma unroll
    for (int off = 16; off; off >>= 1) {
        a += __shfl_xor_sync(0xffffffffu, a, off);
        b += __shfl_xor_sync(0xffffffffu, b, off);
    }
    if ((tid & 31) == 0) { sbuf[tid >> 5] = a; sbuf[8 + (tid >> 5)] = b; }
    __syncthreads();
    if (tid < 8) {
        float wa = sbuf[tid], wb = sbuf[8 + tid];
#pragma unroll
        for (int off = 4; off; off >>= 1) {
            wa += __shfl_xor_sync(0x000000ffu, wa, off);
            wb += __shfl_xor_sync(0x000000ffu, wb, off);
        }
        if (tid == 0) { sbuf[0] = wa; sbuf[8] = wb; }
    }
    __syncthreads();
    ra = sbuf[0];
    rb = sbuf[8];
    __syncthreads();
}

// ---------------------------------------------------------------------------
// Shared symmetric tile-matvec epilogue state.
// ---------------------------------------------------------------------------
struct SMem {
    float sd[8][16][33];
    float scol[8][TS];
    float sbuf[16];
    __align__(16) float pnew[CG_N];   // p vector for this batch (smem-resident)
};

// ---------------------------------------------------------------------------
// R4 symmetric tile body (rows via held regs a0 for batch0, loads batch1).
// spi/spj are SMEM pointers.  Accumulates Ap_dst (atomics) and *pap_dst.
// ---------------------------------------------------------------------------
__device__ __forceinline__ void tile_mv(SMem& sm, const float4* T,
                                        const float4 a0[8],
                                        const float* spi, const float* spj,
                                        int bi, int bj, bool diag,
                                        float* Ap_dst, float* pap_dst)
{
    const int tid  = threadIdx.x;
    const int warp = tid >> 5;
    const int lane = tid & 31;

    const float4 pj4 = reinterpret_cast<const float4*>(spj)[lane];
    float4 cacc = make_float4(0.f, 0.f, 0.f, 0.f);

#pragma unroll
    for (int k = 0; k < 8; ++k) {
        sm.sd[warp][k][lane] = a0[k].x * pj4.x + a0[k].y * pj4.y +
                               a0[k].z * pj4.z + a0[k].w * pj4.w;
        const float pir = spi[16 * warp + k];
        cacc.x += a0[k].x * pir;  cacc.y += a0[k].y * pir;
        cacc.z += a0[k].z * pir;  cacc.w += a0[k].w * pir;
    }
    {
        float4 a[8];
#pragma unroll
        for (int k = 0; k < 8; ++k) a[k] = T[(k + 8) * 32 + lane];
#pragma unroll
        for (int k = 0; k < 8; ++k) {
            sm.sd[warp][k + 8][lane] = a[k].x * pj4.x + a[k].y * pj4.y +
                                       a[k].z * pj4.z + a[k].w * pj4.w;
            const float pir = spi[16 * warp + 8 + k];
            cacc.x += a[k].x * pir;  cacc.y += a[k].y * pir;
            cacc.z += a[k].z * pir;  cacc.w += a[k].w * pir;
        }
    }

    if (!diag) {
        sm.scol[warp][4 * lane + 0] = cacc.x;
        sm.scol[warp][4 * lane + 1] = cacc.y;
        sm.scol[warp][4 * lane + 2] = cacc.z;
        sm.scol[warp][4 * lane + 3] = cacc.w;
    }
    __syncthreads();

    // row dots -> y_bi
    const int ri = tid >> 1;
    const int hi = tid & 1;
    float s = 0.f;
#pragma unroll
    for (int j = 0; j < 16; ++j)
        s += sm.sd[ri >> 4][ri & 15][16 * hi + j];
    s += __shfl_xor_sync(0xffffffffu, s, 1);

    float pap_c = 0.f;
    if (hi == 0) {
        atomicAdd(&Ap_dst[bi * TS + ri], s);
        pap_c = s * spi[ri];
    }

    // transpose part -> y_bj
    if (!diag && tid < TS) {
        float cs = 0.f;
#pragma unroll
        for (int w = 0; w < 8; ++w) cs += sm.scol[w][tid];
        atomicAdd(&Ap_dst[bj * TS + tid], cs);
    }

    if (pap_dst) {
#pragma unroll
        for (int off = 16; off; off >>= 1)
            pap_c += __shfl_xor_sync(0xffffffffu, pap_c, off);
        if (lane == 0) sm.sbuf[warp] = pap_c;
        __syncthreads();
        if (tid == 0) {
            float t = 0.f;
#pragma unroll
            for (int w = 0; w < 8; ++w) t += sm.sbuf[w];
            atomicAdd(pap_dst, diag ? t : 2.f * t);
        }
    }
}

// ---------------------------------------------------------------------------
// mv(x0): plain symmetric matvec of x0 into g_Ap3[2] (must be zero: static
// init on first run, zeroed by K_{maxiter-1} on replays).  No pAp.
// grid=(NPAIR, BS).
// ---------------------------------------------------------------------------
__global__ void __launch_bounds__(256) k_mvx0(const float* __restrict__ x0)
{
    __shared__ SMem sm;
    const int b   = blockIdx.y;
    const int tid = threadIdx.x;

    int li = blockIdx.x, bi = 0;
    while (li >= NT - bi) { li -= NT - bi; ++bi; }
    const int  bj   = bi + li;
    const bool diag = (bi == bj);

    // stage x0 into smem pnew (full vector; only segments bi/bj used)
    reinterpret_cast<float4*>(sm.pnew)[tid] =
        reinterpret_cast<const float4*>(x0 + (size_t)b * CG_N)[tid];
    __syncthreads();

    const float4* T = reinterpret_cast<const float4*>(g_pack) +
                      ((size_t)b * NPAIR + blockIdx.x) * TILE_F4 +
                      (size_t)(tid >> 5) * 16 * 32;
    float4 a0[8];
#pragma unroll
    for (int k = 0; k < 8; ++k) a0[k] = T[k * 32 + (tid & 31)];

    tile_mv(sm, T, a0, sm.pnew + bi * TS, sm.pnew + bj * TS,
            bi, bj, diag, g_Ap3[2] + (size_t)b * CG_N, nullptr);
}

// ---------------------------------------------------------------------------
// Fused iteration kernel K_i, grid=(NPAIR, BS), one launch per iteration.
//   consume  cn = (i+2)%3   (A@p_{i-1}; for i==0 this is A@x0 in slot 2)
//   accum    ac = i%3
//   zero     zr = (i+1)%3
// Every CTA redundantly computes the full update for its batch (exact R4
// arithmetic) -> p_new in SMEM -> tile matvec from SMEM.  No global publish
// of p before use; designated CTAs persist r/p/rz and write out[b][i].
// do_mv==0 (final): update + output only.
// ---------------------------------------------------------------------------
__global__ void __launch_bounds__(256) k_iter(int i,
                                              const float* __restrict__ bvec,
                                              float* __restrict__ out,
                                              int ldout, int do_mv)
{
    __shared__ SMem sm;
    const int b   = blockIdx.y;
    const int tid = threadIdx.x;

    int li = blockIdx.x, bi = 0;
    while (li >= NT - bi) { li -= NT - bi; ++bi; }
    const int  bj   = bi + li;
    const bool diag = (bi == bj);

    const int cn = (i + 2) % 3;
    const int ac = i % 3;
    const int zr = (i + 1) % 3;

    // --- prefetch first tile batch (independent of p) to keep DRAM busy ---
    const float4* T = reinterpret_cast<const float4*>(g_pack) +
                      ((size_t)b * NPAIR + blockIdx.x) * TILE_F4 +
                      (size_t)(tid >> 5) * 16 * 32;
    float4 a0[8];
    if (do_mv) {
#pragma unroll
        for (int k = 0; k < 8; ++k) a0[k] = T[k * 32 + (tid & 31)];
    }

    // --- redundant update for batch b (identical in every CTA) ---
    const float* Apc = g_Ap3[cn] + (size_t)b * CG_N;
    float rv[4], dv[4];
    float rz_p = 0.f, rr_p = 0.f;

    if (i == 0) {
#pragma unroll
        for (int k = 0; k < 4; ++k) {
            const int e = tid + 256 * k;
            const size_t gi = (size_t)b * CG_N + e;
            rv[k] = __ldg(&bvec[gi]) - Apc[e];
            dv[k] = g_d[gi];
            const float zv = dv[k] * rv[k];
            rz_p += rv[k] * zv;
            rr_p += rv[k] * rv[k];
        }
    } else {
        const float rz_old  = g_rz2[(i - 1) & 1][b];
        const float alpha   = rz_old / g_pap3[cn][b];
        const float* r_old  = g_r2[(i - 1) & 1] + (size_t)b * CG_N;
#pragma unroll
        for (int k = 0; k < 4; ++k) {
            const int e = tid + 256 * k;
            rv[k] = r_old[e] - alpha * Apc[e];
            dv[k] = g_d[(size_t)b * CG_N + e];
            const float zv = dv[k] * rv[k];
            rz_p += rv[k] * zv;
            rr_p += rv[k] * rv[k];
        }
    }
    float rz_new, rr;
    block_sum2(sm.sbuf, rz_p, rr_p, rz_new, rr);

    if (i == 0) {
#pragma unroll
        for (int k = 0; k < 4; ++k)
            sm.pnew[tid + 256 * k] = dv[k] * rv[k];
    } else {
        const float beta  = rz_new / g_rz2[(i - 1) & 1][b];
        const float* p_old = g_p2[(i - 1) & 1] + (size_t)b * CG_N;
#pragma unroll
        for (int k = 0; k < 4; ++k) {
            const int e = tid + 256 * k;
            sm.pnew[e] = dv[k] * rv[k] + beta * p_old[e];
        }
    }

    // persist state + output (designated CTA li==0), zero rotation buffers
    if (blockIdx.x == 0) {
        float* rn = g_r2[i & 1] + (size_t)b * CG_N;
        float* pn = g_p2[i & 1] + (size_t)b * CG_N;
#pragma unroll
        for (int k = 0; k < 4; ++k) {
            const int e = tid + 256 * k;
            rn[e] = rv[k];
            pn[e] = (i == 0) ? dv[k] * rv[k]
                             : dv[k] * rv[k] + (rz_new / g_rz2[(i - 1) & 1][b]) *
                               g_p2[(i - 1) & 1][(size_t)b * CG_N + e];
        }
        if (tid == 0) {
            g_rz2[i & 1][b] = rz_new;
            g_pap3[zr][b]   = 0.f;
            out[(size_t)b * ldout + i] = sqrtf(rr);
        }
    }
    if (diag && tid < 32)                          // zero Ap3[zr] segment bi
        reinterpret_cast<float4*>(g_Ap3[zr] + (size_t)b * CG_N + bi * TS)[tid] =
            make_float4(0.f, 0.f, 0.f, 0.f);

    if (!do_mv) return;
    __syncthreads();                               // pnew ready

    // --- symmetric tile matvec from SMEM p_new ---
    tile_mv(sm, T, a0, sm.pnew + bi * TS, sm.pnew + bj * TS,
            bi, bj, diag,
            g_Ap3[ac] + (size_t)b * CG_N, &g_pap3[ac][b]);
}

// ---------------------------------------------------------------------------
// kernel_launch: 2 + (maxiter+1) graph-capturable launches, no device sync.
// ---------------------------------------------------------------------------
extern "C" void kernel_launch(void* const* d_in, const int* in_sizes, int n_in,
                              void* d_out, int out_size)
{
    const float* A    = (const float*)d_in[0];
    const float* bvec = (const float*)d_in[1];
    const float* x0   = (const float*)d_in[2];
    const float* Minv = (const float*)d_in[3];
    float* out        = (float*)d_out;

    const int ldout   = out_size / CG_BS;   // maxiter + 1
    const int maxiter = ldout - 1;

    dim3 grid_pk(CG_N / 8, CG_BS);
    dim3 grid_mv(NPAIR, CG_BS);

    k_pack<<<grid_pk, 256>>>(A, Minv);
    k_mvx0<<<grid_mv, 256>>>(x0);                       // A@x0 -> Ap3[2]

    for (int i = 0; i <= maxiter; ++i)
        k_iter<<<grid_mv, 256>>>(i, bvec, out, ldout, i < maxiter ? 1 : 0);
}

// round 13
// speedup vs baseline: 1.4058x; 1.0234x over previous
#include <cuda_runtime.h>
#include <math.h>

// PyTorchCG: BS=64, N=1024, maxiter derived from out_size.
#define CG_N  1024
#define CG_BS 64
#define TS    128
#define NT    8                    // CG_N / TS
#define NPAIR 36                   // NT*(NT+1)/2
#define TILE_F  (TS * TS)
#define TILE_F4 (TILE_F / 4)

// Persistent state (no allocs -> __device__ globals; zero-initialized).
__device__ float g_r2 [2][CG_BS * CG_N];
__device__ float g_p2 [2][CG_BS * CG_N];
__device__ float g_Ap3[3][CG_BS * CG_N];   // consume / accumulate / zero rotation
__device__ float g_d  [CG_BS * CG_N];      // diag(M_inv)
__device__ float g_rz2[2][CG_BS];
__device__ float g_pap3[3][CG_BS];
// Packed upper-triangle tiles: [b][pair][128x128] contiguous (144 MB scratch).
__device__ __align__(16) float g_pack[(size_t)CG_BS * NPAIR * TILE_F];

// ---------------------------------------------------------------------------
// Pack upper-triangle tiles of A contiguously + extract diag(M_inv).
// grid=(N/8,BS), block=256.
// ---------------------------------------------------------------------------
__global__ void __launch_bounds__(256) k_pack(const float* __restrict__ A,
                                              const float* __restrict__ Minv)
{
    const int b    = blockIdx.y;
    const int warp = threadIdx.x >> 5;
    const int lane = threadIdx.x & 31;
    const int row  = (blockIdx.x << 3) + warp;
    const int bi   = row >> 7;
    const int rloc = row & (TS - 1);

    const float4* Arow =
        reinterpret_cast<const float4*>(A + ((size_t)b * CG_N + row) * CG_N);

    for (int k = bi; k < NT; ++k) {
        float4 a = Arow[lane + 32 * k];
        const int li = bi * NT - (bi * (bi - 1)) / 2 + (k - bi);
        reinterpret_cast<float4*>(g_pack)
            [((size_t)b * NPAIR + li) * TILE_F4 + rloc * 32 + lane] = a;
    }
    if (lane == 0)
        g_d[(size_t)b * CG_N + row] =
            Minv[(size_t)b * CG_N * CG_N + (size_t)row * CG_N + row];
}

// ---------------------------------------------------------------------------
// Deterministic block sum of two values over 256 threads.
// ---------------------------------------------------------------------------
__device__ __forceinline__ void block_sum2(float* sbuf, float a, float b,
                                           float& ra, float& rb)
{
    const int tid = threadIdx.x;
#pragma unroll
    for (int off = 16; off; off >>= 1) {
        a += __shfl_xor_sync(0xffffffffu, a, off);
        b += __shfl_xor_sync(0xffffffffu, b, off);
    }
    if ((tid & 31) == 0) { sbuf[tid >> 5] = a; sbuf[8 + (tid >> 5)] = b; }
    __syncthreads();
    if (tid < 8) {
        float wa = sbuf[tid], wb = sbuf[8 + tid];
#pragma unroll
        for (int off = 4; off; off >>= 1) {
            wa += __shfl_xor_sync(0x000000ffu, wa, off);
            wb += __shfl_xor_sync(0x000000ffu, wb, off);
        }
        if (tid == 0) { sbuf[0] = wa; sbuf[8] = wb; }
    }
    __syncthreads();
    ra = sbuf[0];
    rb = sbuf[8];
    __syncthreads();
}

// ---------------------------------------------------------------------------
// Shared state.
// ---------------------------------------------------------------------------
struct SMem {
    float sd[8][16][33];
    float scol[8][TS];
    float sbuf[16];
    __align__(16) float pnew[CG_N];   // p vector for this batch (smem-resident)
};

// ---------------------------------------------------------------------------
// R4 symmetric tile body; both row batches loaded here (no prefetch held).
// spi/spj point into smem pnew.  Accumulates Ap_dst (atomics) and *pap_dst.
// ---------------------------------------------------------------------------
__device__ __forceinline__ void tile_mv(SMem& sm, const float4* T,
                                        const float* spi, const float* spj,
                                        int bi, int bj, bool diag,
                                        float* Ap_dst, float* pap_dst)
{
    const int tid  = threadIdx.x;
    const int warp = tid >> 5;
    const int lane = tid & 31;

    const float4 pj4 = reinterpret_cast<const float4*>(spj)[lane];
    float4 cacc = make_float4(0.f, 0.f, 0.f, 0.f);

    {
        float4 a[8];
#pragma unroll
        for (int k = 0; k < 8; ++k) a[k] = T[k * 32 + lane];
#pragma unroll
        for (int k = 0; k < 8; ++k) {
            sm.sd[warp][k][lane] = a[k].x * pj4.x + a[k].y * pj4.y +
                                   a[k].z * pj4.z + a[k].w * pj4.w;
            const float pir = spi[16 * warp + k];
            cacc.x += a[k].x * pir;  cacc.y += a[k].y * pir;
            cacc.z += a[k].z * pir;  cacc.w += a[k].w * pir;
        }
    }
    {
        float4 a[8];
#pragma unroll
        for (int k = 0; k < 8; ++k) a[k] = T[(k + 8) * 32 + lane];
#pragma unroll
        for (int k = 0; k < 8; ++k) {
            sm.sd[warp][k + 8][lane] = a[k].x * pj4.x + a[k].y * pj4.y +
                                       a[k].z * pj4.z + a[k].w * pj4.w;
            const float pir = spi[16 * warp + 8 + k];
            cacc.x += a[k].x * pir;  cacc.y += a[k].y * pir;
            cacc.z += a[k].z * pir;  cacc.w += a[k].w * pir;
        }
    }

    if (!diag) {
        sm.scol[warp][4 * lane + 0] = cacc.x;
        sm.scol[warp][4 * lane + 1] = cacc.y;
        sm.scol[warp][4 * lane + 2] = cacc.z;
        sm.scol[warp][4 * lane + 3] = cacc.w;
    }
    __syncthreads();

    // row dots -> y_bi
    const int ri = tid >> 1;
    const int hi = tid & 1;
    float s = 0.f;
#pragma unroll
    for (int j = 0; j < 16; ++j)
        s += sm.sd[ri >> 4][ri & 15][16 * hi + j];
    s += __shfl_xor_sync(0xffffffffu, s, 1);

    float pap_c = 0.f;
    if (hi == 0) {
        atomicAdd(&Ap_dst[bi * TS + ri], s);
        pap_c = s * spi[ri];
    }

    // transpose part -> y_bj
    if (!diag && tid < TS) {
        float cs = 0.f;
#pragma unroll
        for (int w = 0; w < 8; ++w) cs += sm.scol[w][tid];
        atomicAdd(&Ap_dst[bj * TS + tid], cs);
    }

    if (pap_dst) {
#pragma unroll
        for (int off = 16; off; off >>= 1)
            pap_c += __shfl_xor_sync(0xffffffffu, pap_c, off);
        if (lane == 0) sm.sbuf[warp] = pap_c;
        __syncthreads();
        if (tid == 0) {
            float t = 0.f;
#pragma unroll
            for (int w = 0; w < 8; ++w) t += sm.sbuf[w];
            atomicAdd(pap_dst, diag ? t : 2.f * t);
        }
    }
}

// ---------------------------------------------------------------------------
// mv(x0): symmetric matvec of x0 into g_Ap3[2] (zero: static init first run,
// re-zeroed during the iteration ladder on replays).  grid=(NPAIR, BS).
// ---------------------------------------------------------------------------
__global__ void __launch_bounds__(256) k_mvx0(const float* __restrict__ x0)
{
    __shared__ SMem sm;
    const int b   = blockIdx.y;
    const int tid = threadIdx.x;

    int li = blockIdx.x, bi = 0;
    while (li >= NT - bi) { li -= NT - bi; ++bi; }
    const int  bj   = bi + li;
    const bool diag = (bi == bj);

    reinterpret_cast<float4*>(sm.pnew)[tid] =
        reinterpret_cast<const float4*>(x0 + (size_t)b * CG_N)[tid];
    __syncthreads();

    const float4* T = reinterpret_cast<const float4*>(g_pack) +
                      ((size_t)b * NPAIR + blockIdx.x) * TILE_F4 +
                      (size_t)(tid >> 5) * 16 * 32;

    tile_mv(sm, T, sm.pnew + bi * TS, sm.pnew + bj * TS,
            bi, bj, diag, g_Ap3[2] + (size_t)b * CG_N, nullptr);
}

// ---------------------------------------------------------------------------
// Fused iteration kernel K_i, grid=(NPAIR, BS), one launch per iteration.
//   consume cn=(i+2)%3, accum ac=i%3, zero zr=(i+1)%3.
// Every CTA redundantly computes the full update (float4, deterministic,
// identical in all CTAs) -> p_new in SMEM -> tile matvec from SMEM.
// Designated CTA (x==0) persists r/p/rz and writes out[b][i].
// do_mv==0 (final): update + output only.
// ---------------------------------------------------------------------------
__global__ void __launch_bounds__(256) k_iter(int i,
                                              const float* __restrict__ bvec,
                                              float* __restrict__ out,
                                              int ldout, int do_mv)
{
    __shared__ SMem sm;
    const int b   = blockIdx.y;
    const int tid = threadIdx.x;

    int li = blockIdx.x, bi = 0;
    while (li >= NT - bi) { li -= NT - bi; ++bi; }
    const int  bj   = bi + li;
    const bool diag = (bi == bj);

    const int cn = (i + 2) % 3;
    const int ac = i % 3;
    const int zr = (i + 1) % 3;

    // --- redundant update for batch b (float4, identical in every CTA) ---
    const float4* Apc4 = reinterpret_cast<const float4*>(g_Ap3[cn] + (size_t)b * CG_N);
    const float4* d4p  = reinterpret_cast<const float4*>(g_d + (size_t)b * CG_N);

    float4 rv4, z4, pn4;
    float rz_p, rr_p;

    const float4 ap = Apc4[tid];
    const float4 dd = d4p[tid];

    if (i == 0) {
        const float4 bb = reinterpret_cast<const float4*>(bvec + (size_t)b * CG_N)[tid];
        rv4.x = bb.x - ap.x;  rv4.y = bb.y - ap.y;
        rv4.z = bb.z - ap.z;  rv4.w = bb.w - ap.w;
    } else {
        const float alpha = g_rz2[(i - 1) & 1][b] / g_pap3[cn][b];
        const float4 ro = reinterpret_cast<const float4*>(g_r2[(i - 1) & 1] +
                                                          (size_t)b * CG_N)[tid];
        rv4.x = ro.x - alpha * ap.x;  rv4.y = ro.y - alpha * ap.y;
        rv4.z = ro.z - alpha * ap.z;  rv4.w = ro.w - alpha * ap.w;
    }
    z4.x = dd.x * rv4.x;  z4.y = dd.y * rv4.y;
    z4.z = dd.z * rv4.z;  z4.w = dd.w * rv4.w;
    rz_p = rv4.x * z4.x + rv4.y * z4.y + rv4.z * z4.z + rv4.w * z4.w;
    rr_p = rv4.x * rv4.x + rv4.y * rv4.y + rv4.z * rv4.z + rv4.w * rv4.w;

    float rz_new, rr;
    block_sum2(sm.sbuf, rz_p, rr_p, rz_new, rr);

    if (i == 0) {
        pn4 = z4;
    } else {
        const float beta = rz_new / g_rz2[(i - 1) & 1][b];
        const float4 po = reinterpret_cast<const float4*>(g_p2[(i - 1) & 1] +
                                                          (size_t)b * CG_N)[tid];
        pn4.x = z4.x + beta * po.x;  pn4.y = z4.y + beta * po.y;
        pn4.z = z4.z + beta * po.z;  pn4.w = z4.w + beta * po.w;
    }
    reinterpret_cast<float4*>(sm.pnew)[tid] = pn4;

    // persist state + output (designated CTA), zero rotation buffers
    if (blockIdx.x == 0) {
        reinterpret_cast<float4*>(g_r2[i & 1] + (size_t)b * CG_N)[tid] = rv4;
        reinterpret_cast<float4*>(g_p2[i & 1] + (size_t)b * CG_N)[tid] = pn4;
        if (tid == 0) {
            g_rz2[i & 1][b] = rz_new;
            g_pap3[zr][b]   = 0.f;
            out[(size_t)b * ldout + i] = sqrtf(rr);
        }
    }
    if (diag && tid < 32)                          // zero Ap3[zr] segment bi
        reinterpret_cast<float4*>(g_Ap3[zr] + (size_t)b * CG_N + bi * TS)[tid] =
            make_float4(0.f, 0.f, 0.f, 0.f);

    if (!do_mv) return;
    __syncthreads();                               // pnew ready

    // --- symmetric tile matvec from SMEM p_new ---
    const float4* T = reinterpret_cast<const float4*>(g_pack) +
                      ((size_t)b * NPAIR + blockIdx.x) * TILE_F4 +
                      (size_t)(tid >> 5) * 16 * 32;

    tile_mv(sm, T, sm.pnew + bi * TS, sm.pnew + bj * TS,
            bi, bj, diag,
            g_Ap3[ac] + (size_t)b * CG_N, &g_pap3[ac][b]);
}

// ---------------------------------------------------------------------------
// kernel_launch: 2 + (maxiter+1) graph-capturable launches, no device sync.
// ---------------------------------------------------------------------------
extern "C" void kernel_launch(void* const* d_in, const int* in_sizes, int n_in,
                              void* d_out, int out_size)
{
    const float* A    = (const float*)d_in[0];
    const float* bvec = (const float*)d_in[1];
    const float* x0   = (const float*)d_in[2];
    const float* Minv = (const float*)d_in[3];
    float* out        = (float*)d_out;

    const int ldout   = out_size / CG_BS;   // maxiter + 1
    const int maxiter = ldout - 1;

    dim3 grid_pk(CG_N / 8, CG_BS);
    dim3 grid_mv(NPAIR, CG_BS);

    k_pack<<<grid_pk, 256>>>(A, Minv);
    k_mvx0<<<grid_mv, 256>>>(x0);                       // A@x0 -> Ap3[2]

    for (int i = 0; i <= maxiter; ++i)
        k_iter<<<grid_mv, 256>>>(i, bvec, out, ldout, i < maxiter ? 1 : 0);
}